// round 15
// baseline (speedup 1.0000x reference)
#include <cuda_runtime.h>
#include <cuda_fp16.h>
#include <cstdint>

#define N_NODES 8192
#define DIM 256
#define MAXDEG 256   // Binomial(8192,0.01): mean 82, ~19 sigma below 256
#define LSLOT 20     // per-lane edge slots: Poisson(2.56) P(>=20) ~ 1e-11
#define LSTRIDE 21   // odd stride -> conflict-free per-lane smem columns

// ---------------- scratch (__device__ globals; no allocation allowed) ----------
__device__ __align__(16) float  g_M[DIM * DIM];       // Wq^T @ Wk
__device__ __align__(16) float  g_Wvt[DIM * DIM];     // Wv^T
__device__ __align__(16) float  g_U[N_NODES * DIM];   // h @ M              (fp32)
__device__ __align__(16) __half g_Hh[N_NODES * DIM];  // h in fp16 (gather table)
__device__ __align__(16) float  g_Y[N_NODES * DIM];   // h_sum + sum_e w*h_j (fp32)
__device__ __align__(16) float  g_invZ[N_NODES];
__device__ __align__(16) float  g_Hsum[DIM];
__device__ __align__(16) float  g_Hpart[256 * DIM];

// ---------------- helpers --------------------------------------------------------
__device__ __forceinline__ uint32_t f2tf(float x) {
    uint32_t u;
    asm("cvt.rna.tf32.f32 %0, %1;" : "=r"(u) : "f"(x));
    return u;
}

__device__ __forceinline__ uint32_t smem_u32(const void* p) {
    return (uint32_t)__cvta_generic_to_shared(p);
}

#define CP_ASYNC16(dst, src) \
    asm volatile("cp.async.cg.shared.global [%0], [%1], 16;" :: "r"(dst), "l"(src))
#define CP_COMMIT() asm volatile("cp.async.commit_group;" ::: "memory")
#define CP_WAIT0()  asm volatile("cp.async.wait_group 0;" ::: "memory")

// convert 8 packed halves (uint4) into 8 floats, once
__device__ __forceinline__ void cvt8(float* o, uint4 r) {
    union { uint4 u; __half2 b[4]; } v; v.u = r;
    float2 f0 = __half22float2(v.b[0]);
    float2 f1 = __half22float2(v.b[1]);
    float2 f2 = __half22float2(v.b[2]);
    float2 f3 = __half22float2(v.b[3]);
    o[0] = f0.x; o[1] = f0.y; o[2] = f1.x; o[3] = f1.y;
    o[4] = f2.x; o[5] = f2.y; o[6] = f3.x; o[7] = f3.y;
}

#define MMA_TF32(C, A0, A1, A2, A3, B0, B1)                                      \
    asm volatile(                                                                \
        "mma.sync.aligned.m16n8k8.row.col.f32.tf32.tf32.f32 "                    \
        "{%0,%1,%2,%3}, {%4,%5,%6,%7}, {%8,%9}, {%0,%1,%2,%3};"                  \
        : "+f"(C[0]), "+f"(C[1]), "+f"(C[2]), "+f"(C[3])                         \
        : "r"(A0), "r"(A1), "r"(A2), "r"(A3), "r"(B0), "r"(B1))

// ---------------- LAUNCH 1: prep (M, Wvt) | h->fp16 | hsum partials -------------
__global__ void __launch_bounds__(256) setup_kernel(const float* __restrict__ h,
                                                    const float* __restrict__ Wq,
                                                    const float* __restrict__ Wk,
                                                    const float* __restrict__ Wv)
{
    int bx = blockIdx.x;
    int t  = threadIdx.x;

    if (bx < 256) {
        int d = bx, e = t;
        float s = 0.f;
#pragma unroll 8
        for (int o = 0; o < DIM; o++) s += Wq[o * DIM + d] * Wk[o * DIM + e];
        g_M[d * DIM + e] = s;
        g_Wvt[d * DIM + e] = Wv[e * DIM + d];
    } else if (bx < 2304) {
        int idx = (bx - 256) * 256 + t;
        float4 v = reinterpret_cast<const float4*>(h)[idx];
        __half2 p0 = __floats2half2_rn(v.x, v.y);
        __half2 p1 = __floats2half2_rn(v.z, v.w);
        uint2 o;
        o.x = *reinterpret_cast<const unsigned int*>(&p0);
        o.y = *reinterpret_cast<const unsigned int*>(&p1);
        reinterpret_cast<uint2*>(g_Hh)[idx] = o;
    } else {
        int b  = bx - 2304;
        int r0 = b * 32;
        float s = 0.f;
#pragma unroll 8
        for (int r = 0; r < 32; r++) s += h[(size_t)(r0 + r) * DIM + t];
        g_Hpart[b * DIM + t] = s;
    }
}

// ---------------- 3xTF32 GEMM body (R12 config): 64x128, 128 thr, pipelined ------
// smem: A 64x32 stride 36 (9216 B) + B 2x 32x128 stride 132 (33792 B) = 43008 B.
template<int MODE>
__device__ __forceinline__ void gemm_body(int bx, const float* __restrict__ Ain,
                                          float* __restrict__ Cout)
{
    const float* __restrict__ A = (MODE == 0) ? Ain : g_Y;
    const float* __restrict__ B = (MODE == 0) ? g_M : g_Wvt;

    __shared__ float As[64 * 36];
    __shared__ float Bs[2][32 * 132];

    int t    = threadIdx.x;
    int lane = t & 31;
    int w    = t >> 5;
    int wm   = w & 1;
    int wn   = w >> 1;
    int m0   = (bx & 127) * 64;
    int n0   = (bx >> 7) * 128;

    int ar = t >> 3, af = t & 7;              // A loader coords

    float c[2][8][4];
#pragma unroll
    for (int mt = 0; mt < 2; mt++)
#pragma unroll
        for (int nt = 0; nt < 8; nt++)
#pragma unroll
            for (int q = 0; q < 4; q++) c[mt][nt][q] = 0.f;

    float4 areg[4];
    auto ldgA = [&](int k0) {
#pragma unroll
        for (int i = 0; i < 4; i++) {
            int r = ar + 16 * i;
            areg[i] = *reinterpret_cast<const float4*>(
                A + (size_t)(m0 + r) * DIM + k0 + af * 4);
        }
    };
    auto loadB = [&](int st, int k0) {
#pragma unroll
        for (int i = 0; i < 8; i++) {
            int idx = t + 128 * i;
            int r = idx >> 5, f4c = idx & 31;
            uint32_t dst = smem_u32(&Bs[st][r * 132 + f4c * 4]);
            const float* src = B + (size_t)(k0 + r) * DIM + n0 + f4c * 4;
            CP_ASYNC16(dst, src);
        }
        CP_COMMIT();
    };

    ldgA(0);
    loadB(0, 0);

    for (int kt = 0; kt < 8; kt++) {
        int cur = kt & 1;
        __syncthreads();                       // prior compute done reading As
#pragma unroll
        for (int i = 0; i < 4; i++) {
            int r = ar + 16 * i;
            *reinterpret_cast<float4*>(&As[r * 36 + af * 4]) = areg[i];
        }
        CP_WAIT0();                            // B stage cur arrived
        __syncthreads();                       // As + Bs[cur] visible to all
        if (kt < 7) {
            loadB(cur ^ 1, (kt + 1) * 32);
            ldgA((kt + 1) * 32);
        }

#pragma unroll
        for (int kk = 0; kk < 32; kk += 8) {
            uint32_t Ab[2][4], Al[2][4];
#pragma unroll
            for (int mt = 0; mt < 2; mt++) {
                int r  = wm * 32 + mt * 16 + (lane >> 2);
                int cb = kk + (lane & 3);
                float f0 = As[r * 36 + cb];
                float f1 = As[(r + 8) * 36 + cb];
                float f2 = As[r * 36 + cb + 4];
                float f3 = As[(r + 8) * 36 + cb + 4];
                Ab[mt][0] = f2tf(f0); Al[mt][0] = f2tf(f0 - __uint_as_float(Ab[mt][0]));
                Ab[mt][1] = f2tf(f1); Al[mt][1] = f2tf(f1 - __uint_as_float(Ab[mt][1]));
                Ab[mt][2] = f2tf(f2); Al[mt][2] = f2tf(f2 - __uint_as_float(Ab[mt][2]));
                Ab[mt][3] = f2tf(f3); Al[mt][3] = f2tf(f3 - __uint_as_float(Ab[mt][3]));
            }
#pragma unroll
            for (int nt = 0; nt < 8; nt++) {
                int cn = wn * 64 + nt * 8 + (lane >> 2);
                int rk = kk + (lane & 3);
                float g0 = Bs[cur][rk * 132 + cn];
                float g1 = Bs[cur][(rk + 4) * 132 + cn];
                uint32_t Bb0 = f2tf(g0), Bb1 = f2tf(g1);
                uint32_t Bl0 = f2tf(g0 - __uint_as_float(Bb0));
                uint32_t Bl1 = f2tf(g1 - __uint_as_float(Bb1));
#pragma unroll
                for (int mt = 0; mt < 2; mt++) {
                    MMA_TF32(c[mt][nt], Ab[mt][0], Ab[mt][1], Ab[mt][2], Ab[mt][3], Bb0, Bb1);
                    MMA_TF32(c[mt][nt], Ab[mt][0], Ab[mt][1], Ab[mt][2], Ab[mt][3], Bl0, Bl1);
                    MMA_TF32(c[mt][nt], Al[mt][0], Al[mt][1], Al[mt][2], Al[mt][3], Bb0, Bb1);
                }
            }
        }
    }

#pragma unroll
    for (int mt = 0; mt < 2; mt++) {
        int row = m0 + wm * 32 + mt * 16 + (lane >> 2);
        float z0 = 1.f, z1 = 1.f;
        if (MODE == 1) { z0 = g_invZ[row]; z1 = g_invZ[row + 8]; }
#pragma unroll
        for (int nt = 0; nt < 8; nt++) {
            int col = n0 + wn * 64 + nt * 8 + 2 * (lane & 3);
            if (MODE == 0) {
                *reinterpret_cast<float2*>(&g_U[(size_t)row * DIM + col]) =
                    make_float2(c[mt][nt][0], c[mt][nt][1]);
                *reinterpret_cast<float2*>(&g_U[(size_t)(row + 8) * DIM + col]) =
                    make_float2(c[mt][nt][2], c[mt][nt][3]);
            } else {
                *reinterpret_cast<float2*>(&Cout[(size_t)row * DIM + col]) =
                    make_float2(c[mt][nt][0] * z0, c[mt][nt][1] * z0);
                *reinterpret_cast<float2*>(&Cout[(size_t)(row + 8) * DIM + col]) =
                    make_float2(c[mt][nt][2] * z1, c[mt][nt][3] * z1);
            }
        }
    }
}

// ---------------- LAUNCH 2: gemm0 ------------------------------------------------
__global__ void __launch_bounds__(128) gemm0_kernel(const float* __restrict__ h)
{
    gemm_body<0>(blockIdx.x, h, nullptr);
}

// ---------------- LAUNCH 3: hsum final -------------------------------------------
__global__ void hsum_final_kernel()
{
    float s = 0.f;
#pragma unroll 8
    for (int b = 0; b < 256; b++) s += g_Hpart[b * DIM + threadIdx.x];
    g_Hsum[threadIdx.x] = s;
}

// ---------------- LAUNCH 5: gemm1 ------------------------------------------------
__global__ void __launch_bounds__(128) gemm1_kernel(float* __restrict__ out)
{
    gemm_body<1>(blockIdx.x, nullptr, out);
}

// ---------------- LAUNCH 4 (profiled): FUSED scan + attention --------------------
// Warp per row. Phase A: coalesced adj stream (8 uint4 in flight, one branch per
// 8 floats), per-lane private emission, shfl prefix-scan + compaction.
// Phase B: 4-edge batches, fp16 gather converted once, 9-shfl butterfly.
// y_i = Hsum + sum_e (e^s - 1) h_j ;  Z_i = N + sum_e (e^s - 1) ; s = (U_i.h_j)/16
__global__ void __launch_bounds__(128) fused_attn_kernel(const float* __restrict__ adj)
{
    __shared__ int pbuf_s[4][32 * LSTRIDE];   // per-lane private slots
    __shared__ int elist_s[4][MAXDEG];

    int w    = threadIdx.x >> 5;
    int lane = threadIdx.x & 31;
    int i    = blockIdx.x * 4 + w;      // 2048 blocks x 4 warps
    int* pbuf  = &pbuf_s[w][lane * LSTRIDE];
    int* elist = elist_s[w];

    // U_i slice into registers up front
    float ua[8];
    {
        const float4* up = reinterpret_cast<const float4*>(&g_U[(size_t)i * DIM + lane * 8]);
        *reinterpret_cast<float4*>(ua)     = up[0];
        *reinterpret_cast<float4*>(ua + 4) = up[1];
    }

    // ---- Phase A: coalesced scan, MLP=8, branch per 8 floats -------------------
    const uint4* row = reinterpret_cast<const uint4*>(adj + (size_t)i * N_NODES);
    int cntl = 0;
    for (int s0 = 0; s0 < 64; s0 += 8) {
        uint4 v[8];
#pragma unroll
        for (int k = 0; k < 8; k++)
            v[k] = __ldcs(row + lane + (s0 + k) * 32);
#pragma unroll
        for (int k = 0; k < 8; k += 2) {
            uint4 a = v[k], b = v[k + 1];
            if ((a.x | a.y | a.z | a.w) | (b.x | b.y | b.z | b.w)) {  // ~92% skip
                int jb = (lane + (s0 + k) * 32) << 2;
                if (a.x) { if (cntl < LSLOT) pbuf[cntl] = jb;     cntl++; }
                if (a.y) { if (cntl < LSLOT) pbuf[cntl] = jb + 1; cntl++; }
                if (a.z) { if (cntl < LSLOT) pbuf[cntl] = jb + 2; cntl++; }
                if (a.w) { if (cntl < LSLOT) pbuf[cntl] = jb + 3; cntl++; }
                int jc = jb + 128;   // next k-step is +32 uint4 = +128 floats
                if (b.x) { if (cntl < LSLOT) pbuf[cntl] = jc;     cntl++; }
                if (b.y) { if (cntl < LSLOT) pbuf[cntl] = jc + 1; cntl++; }
                if (b.z) { if (cntl < LSLOT) pbuf[cntl] = jc + 2; cntl++; }
                if (b.w) { if (cntl < LSLOT) pbuf[cntl] = jc + 3; cntl++; }
            }
        }
    }
    if (cntl > LSLOT) cntl = LSLOT;

    // exclusive prefix scan of per-lane counts
    int off = cntl;
#pragma unroll
    for (int d = 1; d < 32; d <<= 1) {
        int n = __shfl_up_sync(0xffffffffu, off, d);
        if (lane >= d) off += n;
    }
    int total = __shfl_sync(0xffffffffu, off, 31);
    off -= cntl;
    int ecnt = (total < MAXDEG) ? total : MAXDEG;

    // compact private buffers into contiguous elist
    for (int k = 0; k < cntl; k++) {
        int p = off + k;
        if (p < MAXDEG) elist[p] = pbuf[k];
    }
    __syncwarp();

    // ---- Phase B: batched edge processing --------------------------------------
    float acc[8];
#pragma unroll
    for (int k = 0; k < 8; k++) acc[k] = 0.f;
    float z = 0.f;

    for (int e = 0; e < ecnt; e += 4) {
        int  j0 = elist[e];
        bool b1 = (e + 1) < ecnt, b2 = (e + 2) < ecnt, b3 = (e + 3) < ecnt;
        int  j1 = b1 ? elist[e + 1] : j0;
        int  j2 = b2 ? elist[e + 2] : j0;
        int  j3 = b3 ? elist[e + 3] : j0;

        uint4 r0 = *reinterpret_cast<const uint4*>(&g_Hh[(size_t)j0 * DIM + lane * 8]);
        uint4 r1 = *reinterpret_cast<const uint4*>(&g_Hh[(size_t)j1 * DIM + lane * 8]);
        uint4 r2 = *reinterpret_cast<const uint4*>(&g_Hh[(size_t)j2 * DIM + lane * 8]);
        uint4 r3 = *reinterpret_cast<const uint4*>(&g_Hh[(size_t)j3 * DIM + lane * 8]);

        float e0[8], e1[8], e2[8], e3[8];
        cvt8(e0, r0);
        cvt8(e1, r1);
        cvt8(e2, r2);
        cvt8(e3, r3);

        float p0 = 0.f, p1 = 0.f, p2 = 0.f, p3 = 0.f;
#pragma unroll
        for (int k = 0; k < 8; k++) {
            p0 += ua[k] * e0[k];
            p1 += ua[k] * e1[k];
            p2 += ua[k] * e2[k];
            p3 += ua[k] * e3[k];
        }

        // multi-value butterfly: 4 sums in 9 shfls
        float a0 = p0 + __shfl_xor_sync(0xffffffffu, p0, 16);
        float a1 = p1 + __shfl_xor_sync(0xffffffffu, p1, 16);
        float a2 = p2 + __shfl_xor_sync(0xffffffffu, p2, 16);
        float a3 = p3 + __shfl_xor_sync(0xffffffffu, p3, 16);
        bool hi16 = (lane & 16) != 0;
        float b = hi16 ? a1 : a0;
        float c = hi16 ? a3 : a2;
        b += __shfl_xor_sync(0xffffffffu, b, 8);
        c += __shfl_xor_sync(0xffffffffu, c, 8);
        float d = (lane & 8) ? c : b;
        d += __shfl_xor_sync(0xffffffffu, d, 4);
        d += __shfl_xor_sync(0xffffffffu, d, 2);
        d += __shfl_xor_sync(0xffffffffu, d, 1);

        float wv = __expf(d * 0.0625f) - 1.0f;   // one exp per lane
        float w0 = __shfl_sync(0xffffffffu, wv, 0);
        float w1 = __shfl_sync(0xffffffffu, wv, 16);
        float w2 = __shfl_sync(0xffffffffu, wv, 8);
        float w3 = __shfl_sync(0xffffffffu, wv, 24);
        w1 = b1 ? w1 : 0.f;
        w2 = b2 ? w2 : 0.f;
        w3 = b3 ? w3 : 0.f;
        z += (w0 + w1) + (w2 + w3);

#pragma unroll
        for (int k = 0; k < 8; k++)
            acc[k] += w0 * e0[k] + w1 * e1[k] + w2 * e2[k] + w3 * e3[k];
    }

    const float4* hs = reinterpret_cast<const float4*>(&g_Hsum[lane * 8]);
    float4 h0 = hs[0], h1 = hs[1];
    float4 y0 = make_float4(h0.x + acc[0], h0.y + acc[1], h0.z + acc[2], h0.w + acc[3]);
    float4 y1 = make_float4(h1.x + acc[4], h1.y + acc[5], h1.z + acc[6], h1.w + acc[7]);
    float4* yp = reinterpret_cast<float4*>(&g_Y[(size_t)i * DIM + lane * 8]);
    yp[0] = y0;
    yp[1] = y1;

    if (lane == 0) g_invZ[i] = 1.0f / ((float)N_NODES + z);
}

// ---------------- launch ---------------------------------------------------------
extern "C" void kernel_launch(void* const* d_in, const int* in_sizes, int n_in,
                              void* d_out, int out_size)
{
    const float* adj = (const float*)d_in[0];
    const float* h   = (const float*)d_in[1];
    const float* Wq  = (const float*)d_in[2];
    const float* Wk  = (const float*)d_in[3];
    const float* Wv  = (const float*)d_in[4];
    float* out = (float*)d_out;

    setup_kernel<<<2560, 256>>>(h, Wq, Wk, Wv);   // prep | conv | hsum_part
    gemm0_kernel<<<256, 128>>>(h);                // U = h @ M
    hsum_final_kernel<<<1, 256>>>();
    fused_attn_kernel<<<2048, 128>>>(adj);        // 4th launch -> ncu slot
    gemm1_kernel<<<256, 128>>>(out);
}

// round 16
// speedup vs baseline: 1.0797x; 1.0797x over previous
#include <cuda_runtime.h>
#include <cuda_fp16.h>
#include <cstdint>

#define N_NODES 8192
#define DIM 256
#define MAXDEG 256   // Binomial(8192,0.01): mean 82, ~19 sigma below 256
#define LSLOT 20     // per-lane edge slots: Poisson(2.56) P(>=20) ~ 1e-11
#define LSTRIDE 21   // odd stride -> conflict-free per-lane smem columns

// ---------------- scratch (__device__ globals; no allocation allowed) ----------
__device__ __align__(16) float  g_M[DIM * DIM];       // Wq^T @ Wk
__device__ __align__(16) float  g_Wvt[DIM * DIM];     // Wv^T
__device__ __align__(16) float  g_U[N_NODES * DIM];   // h @ M              (fp32)
__device__ __align__(16) __half g_Hh[(N_NODES + 8) * DIM];  // h fp16 + 8 zero pad rows
__device__ __align__(16) float  g_Y[N_NODES * DIM];   // h_sum + sum_e w*h_j (fp32)
__device__ __align__(16) float  g_invZ[N_NODES];
__device__ __align__(16) float  g_Hsum[DIM];
__device__ __align__(16) float  g_Hpart[256 * DIM];

// ---------------- helpers --------------------------------------------------------
__device__ __forceinline__ uint32_t f2tf(float x) {
    uint32_t u;
    asm("cvt.rna.tf32.f32 %0, %1;" : "=r"(u) : "f"(x));
    return u;
}

__device__ __forceinline__ uint32_t smem_u32(const void* p) {
    return (uint32_t)__cvta_generic_to_shared(p);
}

#define CP_ASYNC16(dst, src) \
    asm volatile("cp.async.cg.shared.global [%0], [%1], 16;" :: "r"(dst), "l"(src))
#define CP_COMMIT() asm volatile("cp.async.commit_group;" ::: "memory")
#define CP_WAIT0()  asm volatile("cp.async.wait_group 0;" ::: "memory")

// convert 8 packed halves (uint4) into 8 floats, once
__device__ __forceinline__ void cvt8(float* o, uint4 r) {
    union { uint4 u; __half2 b[4]; } v; v.u = r;
    float2 f0 = __half22float2(v.b[0]);
    float2 f1 = __half22float2(v.b[1]);
    float2 f2 = __half22float2(v.b[2]);
    float2 f3 = __half22float2(v.b[3]);
    o[0] = f0.x; o[1] = f0.y; o[2] = f1.x; o[3] = f1.y;
    o[4] = f2.x; o[5] = f2.y; o[6] = f3.x; o[7] = f3.y;
}

#define MMA_TF32(C, A0, A1, A2, A3, B0, B1)                                      \
    asm volatile(                                                                \
        "mma.sync.aligned.m16n8k8.row.col.f32.tf32.tf32.f32 "                    \
        "{%0,%1,%2,%3}, {%4,%5,%6,%7}, {%8,%9}, {%0,%1,%2,%3};"                  \
        : "+f"(C[0]), "+f"(C[1]), "+f"(C[2]), "+f"(C[3])                         \
        : "r"(A0), "r"(A1), "r"(A2), "r"(A3), "r"(B0), "r"(B1))

// ---------------- LAUNCH 1: prep | h->fp16 | hsum partials | zero pad rows ------
__global__ void __launch_bounds__(256) setup_kernel(const float* __restrict__ h,
                                                    const float* __restrict__ Wq,
                                                    const float* __restrict__ Wk,
                                                    const float* __restrict__ Wv)
{
    int bx = blockIdx.x;
    int t  = threadIdx.x;

    if (bx < 256) {
        int d = bx, e = t;
        float s = 0.f;
#pragma unroll 8
        for (int o = 0; o < DIM; o++) s += Wq[o * DIM + d] * Wk[o * DIM + e];
        g_M[d * DIM + e] = s;
        g_Wvt[d * DIM + e] = Wv[e * DIM + d];
    } else if (bx < 2304) {
        int idx = (bx - 256) * 256 + t;
        float4 v = reinterpret_cast<const float4*>(h)[idx];
        __half2 p0 = __floats2half2_rn(v.x, v.y);
        __half2 p1 = __floats2half2_rn(v.z, v.w);
        uint2 o;
        o.x = *reinterpret_cast<const unsigned int*>(&p0);
        o.y = *reinterpret_cast<const unsigned int*>(&p1);
        reinterpret_cast<uint2*>(g_Hh)[idx] = o;
    } else if (bx < 2560) {
        int b  = bx - 2304;
        int r0 = b * 32;
        float s = 0.f;
#pragma unroll 8
        for (int r = 0; r < 32; r++) s += h[(size_t)(r0 + r) * DIM + t];
        g_Hpart[b * DIM + t] = s;
    } else {
        // zero the 8 pad rows: 8*256 halves = 256 uint4
        reinterpret_cast<uint4*>(&g_Hh[(size_t)N_NODES * DIM])[t] =
            make_uint4(0u, 0u, 0u, 0u);
    }
}

// ---------------- 3xTF32 GEMM body (R12 config): 64x128, 128 thr, pipelined ------
// smem: A 64x32 stride 36 (9216 B) + B 2x 32x128 stride 132 (33792 B) = 43008 B.
template<int MODE>
__device__ __forceinline__ void gemm_body(int bx, const float* __restrict__ Ain,
                                          float* __restrict__ Cout)
{
    const float* __restrict__ A = (MODE == 0) ? Ain : g_Y;
    const float* __restrict__ B = (MODE == 0) ? g_M : g_Wvt;

    __shared__ float As[64 * 36];
    __shared__ float Bs[2][32 * 132];

    int t    = threadIdx.x;
    int lane = t & 31;
    int w    = t >> 5;
    int wm   = w & 1;
    int wn   = w >> 1;
    int m0   = (bx & 127) * 64;
    int n0   = (bx >> 7) * 128;

    int ar = t >> 3, af = t & 7;              // A loader coords

    float c[2][8][4];
#pragma unroll
    for (int mt = 0; mt < 2; mt++)
#pragma unroll
        for (int nt = 0; nt < 8; nt++)
#pragma unroll
            for (int q = 0; q < 4; q++) c[mt][nt][q] = 0.f;

    float4 areg[4];
    auto ldgA = [&](int k0) {
#pragma unroll
        for (int i = 0; i < 4; i++) {
            int r = ar + 16 * i;
            areg[i] = *reinterpret_cast<const float4*>(
                A + (size_t)(m0 + r) * DIM + k0 + af * 4);
        }
    };
    auto loadB = [&](int st, int k0) {
#pragma unroll
        for (int i = 0; i < 8; i++) {
            int idx = t + 128 * i;
            int r = idx >> 5, f4c = idx & 31;
            uint32_t dst = smem_u32(&Bs[st][r * 132 + f4c * 4]);
            const float* src = B + (size_t)(k0 + r) * DIM + n0 + f4c * 4;
            CP_ASYNC16(dst, src);
        }
        CP_COMMIT();
    };

    ldgA(0);
    loadB(0, 0);

    for (int kt = 0; kt < 8; kt++) {
        int cur = kt & 1;
        __syncthreads();                       // prior compute done reading As
#pragma unroll
        for (int i = 0; i < 4; i++) {
            int r = ar + 16 * i;
            *reinterpret_cast<float4*>(&As[r * 36 + af * 4]) = areg[i];
        }
        CP_WAIT0();                            // B stage cur arrived
        __syncthreads();                       // As + Bs[cur] visible to all
        if (kt < 7) {
            loadB(cur ^ 1, (kt + 1) * 32);
            ldgA((kt + 1) * 32);
        }

#pragma unroll
        for (int kk = 0; kk < 32; kk += 8) {
            uint32_t Ab[2][4], Al[2][4];
#pragma unroll
            for (int mt = 0; mt < 2; mt++) {
                int r  = wm * 32 + mt * 16 + (lane >> 2);
                int cb = kk + (lane & 3);
                float f0 = As[r * 36 + cb];
                float f1 = As[(r + 8) * 36 + cb];
                float f2 = As[r * 36 + cb + 4];
                float f3 = As[(r + 8) * 36 + cb + 4];
                Ab[mt][0] = f2tf(f0); Al[mt][0] = f2tf(f0 - __uint_as_float(Ab[mt][0]));
                Ab[mt][1] = f2tf(f1); Al[mt][1] = f2tf(f1 - __uint_as_float(Ab[mt][1]));
                Ab[mt][2] = f2tf(f2); Al[mt][2] = f2tf(f2 - __uint_as_float(Ab[mt][2]));
                Ab[mt][3] = f2tf(f3); Al[mt][3] = f2tf(f3 - __uint_as_float(Ab[mt][3]));
            }
#pragma unroll
            for (int nt = 0; nt < 8; nt++) {
                int cn = wn * 64 + nt * 8 + (lane >> 2);
                int rk = kk + (lane & 3);
                float g0 = Bs[cur][rk * 132 + cn];
                float g1 = Bs[cur][(rk + 4) * 132 + cn];
                uint32_t Bb0 = f2tf(g0), Bb1 = f2tf(g1);
                uint32_t Bl0 = f2tf(g0 - __uint_as_float(Bb0));
                uint32_t Bl1 = f2tf(g1 - __uint_as_float(Bb1));
#pragma unroll
                for (int mt = 0; mt < 2; mt++) {
                    MMA_TF32(c[mt][nt], Ab[mt][0], Ab[mt][1], Ab[mt][2], Ab[mt][3], Bb0, Bb1);
                    MMA_TF32(c[mt][nt], Ab[mt][0], Ab[mt][1], Ab[mt][2], Ab[mt][3], Bl0, Bl1);
                    MMA_TF32(c[mt][nt], Al[mt][0], Al[mt][1], Al[mt][2], Al[mt][3], Bb0, Bb1);
                }
            }
        }
    }

#pragma unroll
    for (int mt = 0; mt < 2; mt++) {
        int row = m0 + wm * 32 + mt * 16 + (lane >> 2);
        float z0 = 1.f, z1 = 1.f;
        if (MODE == 1) { z0 = g_invZ[row]; z1 = g_invZ[row + 8]; }
#pragma unroll
        for (int nt = 0; nt < 8; nt++) {
            int col = n0 + wn * 64 + nt * 8 + 2 * (lane & 3);
            if (MODE == 0) {
                *reinterpret_cast<float2*>(&g_U[(size_t)row * DIM + col]) =
                    make_float2(c[mt][nt][0], c[mt][nt][1]);
                *reinterpret_cast<float2*>(&g_U[(size_t)(row + 8) * DIM + col]) =
                    make_float2(c[mt][nt][2], c[mt][nt][3]);
            } else {
                *reinterpret_cast<float2*>(&Cout[(size_t)row * DIM + col]) =
                    make_float2(c[mt][nt][0] * z0, c[mt][nt][1] * z0);
                *reinterpret_cast<float2*>(&Cout[(size_t)(row + 8) * DIM + col]) =
                    make_float2(c[mt][nt][2] * z1, c[mt][nt][3] * z1);
            }
        }
    }
}

// ---------------- LAUNCH 2: gemm0 (256 tiles) + hsum_final (block 256) ----------
__global__ void __launch_bounds__(128) gemm0_kernel(const float* __restrict__ h)
{
    int bx = blockIdx.x;
    if (bx < 256) {
        gemm_body<0>(bx, h, nullptr);
    } else {
        for (int cidx = threadIdx.x; cidx < DIM; cidx += 128) {
            float s = 0.f;
#pragma unroll 8
            for (int b = 0; b < 256; b++) s += g_Hpart[b * DIM + cidx];
            g_Hsum[cidx] = s;
        }
    }
}

// ---------------- LAUNCH 4 (profiled): gemm1 -------------------------------------
__global__ void __launch_bounds__(128) gemm1_kernel(float* __restrict__ out)
{
    gemm_body<1>(blockIdx.x, nullptr, out);
}

// ---------------- LAUNCH 3: FUSED scan + attention -------------------------------
// Warp per row. Phase A: coalesced adj stream (MLP=8), per-lane private emission,
// shfl prefix-scan + compaction, pad elist to multiple of 8 with zero-row index.
// Phase B: 8 edges per iteration, ALL loads up front, branch-free (padding makes
// out-of-range edges contribute exactly 0: dot=0 -> expf(0)-1 = 0).
// y_i = Hsum + sum_e (e^s - 1) h_j ;  Z_i = N + sum_e (e^s - 1) ; s = (U_i.h_j)/16
__global__ void __launch_bounds__(128) fused_attn_kernel(const float* __restrict__ adj)
{
    __shared__ int pbuf_s[4][32 * LSTRIDE];   // per-lane private slots
    __shared__ int elist_s[4][MAXDEG + 8];

    int w    = threadIdx.x >> 5;
    int lane = threadIdx.x & 31;
    int i    = blockIdx.x * 4 + w;      // 2048 blocks x 4 warps
    int* pbuf  = &pbuf_s[w][lane * LSTRIDE];
    int* elist = elist_s[w];

    // U_i slice into registers up front
    float ua[8];
    {
        const float4* up = reinterpret_cast<const float4*>(&g_U[(size_t)i * DIM + lane * 8]);
        *reinterpret_cast<float4*>(ua)     = up[0];
        *reinterpret_cast<float4*>(ua + 4) = up[1];
    }

    // ---- Phase A: coalesced scan, MLP=8, branch per 8 floats -------------------
    const uint4* row = reinterpret_cast<const uint4*>(adj + (size_t)i * N_NODES);
    int cntl = 0;
    for (int s0 = 0; s0 < 64; s0 += 8) {
        uint4 v[8];
#pragma unroll
        for (int k = 0; k < 8; k++)
            v[k] = __ldcs(row + lane + (s0 + k) * 32);
#pragma unroll
        for (int k = 0; k < 8; k += 2) {
            uint4 a = v[k], b = v[k + 1];
            if ((a.x | a.y | a.z | a.w) | (b.x | b.y | b.z | b.w)) {  // ~92% skip
                int jb = (lane + (s0 + k) * 32) << 2;
                if (a.x) { if (cntl < LSLOT) pbuf[cntl] = jb;     cntl++; }
                if (a.y) { if (cntl < LSLOT) pbuf[cntl] = jb + 1; cntl++; }
                if (a.z) { if (cntl < LSLOT) pbuf[cntl] = jb + 2; cntl++; }
                if (a.w) { if (cntl < LSLOT) pbuf[cntl] = jb + 3; cntl++; }
                int jc = jb + 128;   // next k-step is +32 uint4 = +128 floats
                if (b.x) { if (cntl < LSLOT) pbuf[cntl] = jc;     cntl++; }
                if (b.y) { if (cntl < LSLOT) pbuf[cntl] = jc + 1; cntl++; }
                if (b.z) { if (cntl < LSLOT) pbuf[cntl] = jc + 2; cntl++; }
                if (b.w) { if (cntl < LSLOT) pbuf[cntl] = jc + 3; cntl++; }
            }
        }
    }
    if (cntl > LSLOT) cntl = LSLOT;

    // exclusive prefix scan of per-lane counts
    int off = cntl;
#pragma unroll
    for (int d = 1; d < 32; d <<= 1) {
        int n = __shfl_up_sync(0xffffffffu, off, d);
        if (lane >= d) off += n;
    }
    int total = __shfl_sync(0xffffffffu, off, 31);
    off -= cntl;
    int ecnt = (total < MAXDEG) ? total : MAXDEG;

    // compact private buffers into contiguous elist
    for (int k = 0; k < cntl; k++) {
        int p = off + k;
        if (p < MAXDEG) elist[p] = pbuf[k];
    }
    __syncwarp();

    // pad to multiple of 8 with the zero-row index (contributes exactly 0)
    int padded = (ecnt + 7) & ~7;
    if (ecnt + lane < padded) elist[ecnt + lane] = N_NODES;
    __syncwarp();

    // ---- Phase B: 8 edges / iteration, branch-free -----------------------------
    float acc[8];
#pragma unroll
    for (int k = 0; k < 8; k++) acc[k] = 0.f;
    float z = 0.f;

    for (int e = 0; e < padded; e += 8) {
        uint4 r[8];
#pragma unroll
        for (int q = 0; q < 8; q++) {
            int j = elist[e + q];
            r[q] = *reinterpret_cast<const uint4*>(&g_Hh[(size_t)j * DIM + lane * 8]);
        }

#pragma unroll
        for (int g = 0; g < 2; g++) {
            float e0[8], e1[8], e2[8], e3[8];
            cvt8(e0, r[4 * g + 0]);
            cvt8(e1, r[4 * g + 1]);
            cvt8(e2, r[4 * g + 2]);
            cvt8(e3, r[4 * g + 3]);

            float p0 = 0.f, p1 = 0.f, p2 = 0.f, p3 = 0.f;
#pragma unroll
            for (int k = 0; k < 8; k++) {
                p0 += ua[k] * e0[k];
                p1 += ua[k] * e1[k];
                p2 += ua[k] * e2[k];
                p3 += ua[k] * e3[k];
            }

            // multi-value butterfly: 4 sums in 9 shfls
            float a0 = p0 + __shfl_xor_sync(0xffffffffu, p0, 16);
            float a1 = p1 + __shfl_xor_sync(0xffffffffu, p1, 16);
            float a2 = p2 + __shfl_xor_sync(0xffffffffu, p2, 16);
            float a3 = p3 + __shfl_xor_sync(0xffffffffu, p3, 16);
            bool hi16 = (lane & 16) != 0;
            float b = hi16 ? a1 : a0;
            float c = hi16 ? a3 : a2;
            b += __shfl_xor_sync(0xffffffffu, b, 8);
            c += __shfl_xor_sync(0xffffffffu, c, 8);
            float d = (lane & 8) ? c : b;
            d += __shfl_xor_sync(0xffffffffu, d, 4);
            d += __shfl_xor_sync(0xffffffffu, d, 2);
            d += __shfl_xor_sync(0xffffffffu, d, 1);

            float wv = __expf(d * 0.0625f) - 1.0f;   // one exp per lane
            float w0 = __shfl_sync(0xffffffffu, wv, 0);
            float w1 = __shfl_sync(0xffffffffu, wv, 16);
            float w2 = __shfl_sync(0xffffffffu, wv, 8);
            float w3 = __shfl_sync(0xffffffffu, wv, 24);
            z += (w0 + w1) + (w2 + w3);

#pragma unroll
            for (int k = 0; k < 8; k++)
                acc[k] += w0 * e0[k] + w1 * e1[k] + w2 * e2[k] + w3 * e3[k];
        }
    }

    const float4* hs = reinterpret_cast<const float4*>(&g_Hsum[lane * 8]);
    float4 h0 = hs[0], h1 = hs[1];
    float4 y0 = make_float4(h0.x + acc[0], h0.y + acc[1], h0.z + acc[2], h0.w + acc[3]);
    float4 y1 = make_float4(h1.x + acc[4], h1.y + acc[5], h1.z + acc[6], h1.w + acc[7]);
    float4* yp = reinterpret_cast<float4*>(&g_Y[(size_t)i * DIM + lane * 8]);
    yp[0] = y0;
    yp[1] = y1;

    if (lane == 0) g_invZ[i] = 1.0f / ((float)N_NODES + z);
}

// ---------------- launch ---------------------------------------------------------
extern "C" void kernel_launch(void* const* d_in, const int* in_sizes, int n_in,
                              void* d_out, int out_size)
{
    const float* adj = (const float*)d_in[0];
    const float* h   = (const float*)d_in[1];
    const float* Wq  = (const float*)d_in[2];
    const float* Wk  = (const float*)d_in[3];
    const float* Wv  = (const float*)d_in[4];
    float* out = (float*)d_out;

    setup_kernel<<<2561, 256>>>(h, Wq, Wk, Wv);   // prep | conv | hsum_part | pad
    gemm0_kernel<<<257, 128>>>(h);                // U = h @ M | hsum_final
    fused_attn_kernel<<<2048, 128>>>(adj);
    gemm1_kernel<<<256, 128>>>(out);              // 4th launch -> ncu slot
}

// round 17
// speedup vs baseline: 1.0831x; 1.0031x over previous
#include <cuda_runtime.h>
#include <cuda_fp16.h>
#include <cstdint>

#define N_NODES 8192
#define DIM 256
#define MAXDEG 256   // Binomial(8192,0.01): mean 82, ~19 sigma below 256
#define LSLOT 20     // per-lane edge slots: Poisson(2.56) P(>=20) ~ 1e-11
#define LSTRIDE 21   // odd stride -> conflict-free per-lane smem columns

// ---------------- scratch (__device__ globals; no allocation allowed) ----------
__device__ __align__(16) __half g_Mht[DIM * DIM];     // M^T in fp16: Mht[e][d] = (Wq^T Wk)[d][e]
__device__ __align__(16) float  g_Wvt[DIM * DIM];     // Wv^T (fp32, for exact out GEMM)
__device__ __align__(16) float  g_U[N_NODES * DIM];   // h @ M              (fp32)
__device__ __align__(16) __half g_Hh[(N_NODES + 8) * DIM];  // h fp16 + 8 zero pad rows
__device__ __align__(16) float  g_Y[N_NODES * DIM];   // h_sum + sum_e w*h_j (fp32)
__device__ __align__(16) float  g_invZ[N_NODES];
__device__ __align__(16) float  g_Hsum[DIM];
__device__ __align__(16) float  g_Hpart[256 * DIM];

// ---------------- helpers --------------------------------------------------------
__device__ __forceinline__ uint32_t f2tf(float x) {
    uint32_t u;
    asm("cvt.rna.tf32.f32 %0, %1;" : "=r"(u) : "f"(x));
    return u;
}

__device__ __forceinline__ uint32_t smem_u32(const void* p) {
    return (uint32_t)__cvta_generic_to_shared(p);
}

#define CP_ASYNC16(dst, src) \
    asm volatile("cp.async.cg.shared.global [%0], [%1], 16;" :: "r"(dst), "l"(src))
#define CP_COMMIT() asm volatile("cp.async.commit_group;" ::: "memory")
#define CP_WAIT0()  asm volatile("cp.async.wait_group 0;" ::: "memory")

// convert 8 packed halves (uint4) into 8 floats, once
__device__ __forceinline__ void cvt8(float* o, uint4 r) {
    union { uint4 u; __half2 b[4]; } v; v.u = r;
    float2 f0 = __half22float2(v.b[0]);
    float2 f1 = __half22float2(v.b[1]);
    float2 f2 = __half22float2(v.b[2]);
    float2 f3 = __half22float2(v.b[3]);
    o[0] = f0.x; o[1] = f0.y; o[2] = f1.x; o[3] = f1.y;
    o[4] = f2.x; o[5] = f2.y; o[6] = f3.x; o[7] = f3.y;
}

#define MMA_TF32(C, A0, A1, A2, A3, B0, B1)                                      \
    asm volatile(                                                                \
        "mma.sync.aligned.m16n8k8.row.col.f32.tf32.tf32.f32 "                    \
        "{%0,%1,%2,%3}, {%4,%5,%6,%7}, {%8,%9}, {%0,%1,%2,%3};"                  \
        : "+f"(C[0]), "+f"(C[1]), "+f"(C[2]), "+f"(C[3])                         \
        : "r"(A0), "r"(A1), "r"(A2), "r"(A3), "r"(B0), "r"(B1))

#define MMA_F16(C, A0, A1, A2, A3, B0, B1)                                       \
    asm volatile(                                                                \
        "mma.sync.aligned.m16n8k16.row.col.f32.f16.f16.f32 "                     \
        "{%0,%1,%2,%3}, {%4,%5,%6,%7}, {%8,%9}, {%0,%1,%2,%3};"                  \
        : "+f"(C[0]), "+f"(C[1]), "+f"(C[2]), "+f"(C[3])                         \
        : "r"(A0), "r"(A1), "r"(A2), "r"(A3), "r"(B0), "r"(B1))

// ---------------- LAUNCH 1: prep | h->fp16 | hsum partials | zero pad rows ------
__global__ void __launch_bounds__(256) setup_kernel(const float* __restrict__ h,
                                                    const float* __restrict__ Wq,
                                                    const float* __restrict__ Wk,
                                                    const float* __restrict__ Wv)
{
    int bx = blockIdx.x;
    int t  = threadIdx.x;

    if (bx < 256) {
        // Mht[e][d] = sum_o Wq[o][d] * Wk[o][e]; block = e, thread = d
        int e = bx, d = t;
        float s = 0.f;
#pragma unroll 8
        for (int o = 0; o < DIM; o++) s += Wq[o * DIM + d] * Wk[o * DIM + e];
        g_Mht[e * DIM + d] = __float2half(s);            // coalesced
        g_Wvt[d * DIM + e] = Wv[e * DIM + d];            // coalesced read
    } else if (bx < 2304) {
        int idx = (bx - 256) * 256 + t;
        float4 v = reinterpret_cast<const float4*>(h)[idx];
        __half2 p0 = __floats2half2_rn(v.x, v.y);
        __half2 p1 = __floats2half2_rn(v.z, v.w);
        uint2 o;
        o.x = *reinterpret_cast<const unsigned int*>(&p0);
        o.y = *reinterpret_cast<const unsigned int*>(&p1);
        reinterpret_cast<uint2*>(g_Hh)[idx] = o;
    } else if (bx < 2560) {
        int b  = bx - 2304;
        int r0 = b * 32;
        float s = 0.f;
#pragma unroll 8
        for (int r = 0; r < 32; r++) s += h[(size_t)(r0 + r) * DIM + t];
        g_Hpart[b * DIM + t] = s;
    } else {
        // zero the 8 pad rows: 8*256 halves = 256 uint4
        reinterpret_cast<uint4*>(&g_Hh[(size_t)N_NODES * DIM])[t] =
            make_uint4(0u, 0u, 0u, 0u);
    }
}

// ---------------- LAUNCH 2: gemm0 fp16 (U = Hh @ Mht^T) + hsum_final -------------
// 64x128 tile, 128 threads, m16n8k16 fp16 MMA, both operands cp.async
// double-buffered. smem halves stride 40 (80B rows: 16B-aligned, conflict-free).
__global__ void __launch_bounds__(128) gemm0_kernel(const float* __restrict__ hunused)
{
    int bx = blockIdx.x;
    if (bx >= 256) {
        for (int cidx = threadIdx.x; cidx < DIM; cidx += 128) {
            float s = 0.f;
#pragma unroll 8
            for (int b = 0; b < 256; b++) s += g_Hpart[b * DIM + cidx];
            g_Hsum[cidx] = s;
        }
        return;
    }

    __shared__ __half As[2][64 * 40];     // [row][k] 64x32 halves + pad
    __shared__ __half Bs[2][128 * 40];    // [n][k]  128x32 halves + pad

    int t    = threadIdx.x;
    int lane = t & 31;
    int w    = t >> 5;
    int wm   = w & 1;
    int wn   = w >> 1;
    int m0   = (bx & 127) * 64;
    int n0   = (bx >> 7) * 128;

    float c[2][8][4];
#pragma unroll
    for (int mt = 0; mt < 2; mt++)
#pragma unroll
        for (int nt = 0; nt < 8; nt++)
#pragma unroll
            for (int q = 0; q < 4; q++) c[mt][nt][q] = 0.f;

    int arow = t >> 1, apart = t & 1;     // A: 64 rows x 2 halves-of-row

    auto load_stage = [&](int st, int k0) {
        // A: 16 halves (2x16B) per thread
        {
            uint32_t dst = smem_u32(&As[st][arow * 40 + apart * 16]);
            const __half* src = &g_Hh[(size_t)(m0 + arow) * DIM + k0 + apart * 16];
            CP_ASYNC16(dst, src);
            CP_ASYNC16(dst + 16, src + 8);
        }
        // B: one n-row (32 halves = 4x16B) per thread
        {
            uint32_t dst = smem_u32(&Bs[st][t * 40]);
            const __half* src = &g_Mht[(size_t)(n0 + t) * DIM + k0];
#pragma unroll
            for (int i = 0; i < 4; i++)
                CP_ASYNC16(dst + 16 * i, src + 8 * i);
        }
        CP_COMMIT();
    };

    load_stage(0, 0);

    for (int kt = 0; kt < 8; kt++) {
        int cur = kt & 1;
        CP_WAIT0();
        __syncthreads();                   // stage cur ready; prior compute done
        if (kt < 7) load_stage(cur ^ 1, (kt + 1) * 32);

        const uint32_t* A32 = reinterpret_cast<const uint32_t*>(As[cur]);
        const uint32_t* B32 = reinterpret_cast<const uint32_t*>(Bs[cur]);

#pragma unroll
        for (int kk2 = 0; kk2 < 16; kk2 += 8) {    // two k16 steps (u32 units)
            uint32_t Af[2][4];
#pragma unroll
            for (int mt = 0; mt < 2; mt++) {
                int r = wm * 32 + mt * 16 + (lane >> 2);
                int cb = kk2 + (lane & 3);
                Af[mt][0] = A32[r * 20 + cb];
                Af[mt][1] = A32[(r + 8) * 20 + cb];
                Af[mt][2] = A32[r * 20 + cb + 4];
                Af[mt][3] = A32[(r + 8) * 20 + cb + 4];
            }
#pragma unroll
            for (int nt = 0; nt < 8; nt++) {
                int cn = wn * 64 + nt * 8 + (lane >> 2);
                int cb = kk2 + (lane & 3);
                uint32_t B0 = B32[cn * 20 + cb];
                uint32_t B1 = B32[cn * 20 + cb + 4];
#pragma unroll
                for (int mt = 0; mt < 2; mt++)
                    MMA_F16(c[mt][nt], Af[mt][0], Af[mt][1], Af[mt][2], Af[mt][3], B0, B1);
            }
        }
    }

#pragma unroll
    for (int mt = 0; mt < 2; mt++) {
        int row = m0 + wm * 32 + mt * 16 + (lane >> 2);
#pragma unroll
        for (int nt = 0; nt < 8; nt++) {
            int col = n0 + wn * 64 + nt * 8 + 2 * (lane & 3);
            *reinterpret_cast<float2*>(&g_U[(size_t)row * DIM + col]) =
                make_float2(c[mt][nt][0], c[mt][nt][1]);
            *reinterpret_cast<float2*>(&g_U[(size_t)(row + 8) * DIM + col]) =
                make_float2(c[mt][nt][2], c[mt][nt][3]);
        }
    }
}

// ---------------- LAUNCH 4 (profiled): gemm1 3xTF32 (out = diag(invZ) Y Wv^T) ----
// smem: A 64x32 stride 36 (9216 B) + B 2x 32x128 stride 132 (33792 B) = 43008 B.
__global__ void __launch_bounds__(128) gemm1_kernel(float* __restrict__ Cout)
{
    const float* __restrict__ A = g_Y;
    const float* __restrict__ B = g_Wvt;
    int bx = blockIdx.x;

    __shared__ float As[64 * 36];
    __shared__ float Bs[2][32 * 132];

    int t    = threadIdx.x;
    int lane = t & 31;
    int w    = t >> 5;
    int wm   = w & 1;
    int wn   = w >> 1;
    int m0   = (bx & 127) * 64;
    int n0   = (bx >> 7) * 128;

    int ar = t >> 3, af = t & 7;

    float c[2][8][4];
#pragma unroll
    for (int mt = 0; mt < 2; mt++)
#pragma unroll
        for (int nt = 0; nt < 8; nt++)
#pragma unroll
            for (int q = 0; q < 4; q++) c[mt][nt][q] = 0.f;

    float4 areg[4];
    auto ldgA = [&](int k0) {
#pragma unroll
        for (int i = 0; i < 4; i++) {
            int r = ar + 16 * i;
            areg[i] = *reinterpret_cast<const float4*>(
                A + (size_t)(m0 + r) * DIM + k0 + af * 4);
        }
    };
    auto loadB = [&](int st, int k0) {
#pragma unroll
        for (int i = 0; i < 8; i++) {
            int idx = t + 128 * i;
            int r = idx >> 5, f4c = idx & 31;
            uint32_t dst = smem_u32(&Bs[st][r * 132 + f4c * 4]);
            const float* src = B + (size_t)(k0 + r) * DIM + n0 + f4c * 4;
            CP_ASYNC16(dst, src);
        }
        CP_COMMIT();
    };

    ldgA(0);
    loadB(0, 0);

    for (int kt = 0; kt < 8; kt++) {
        int cur = kt & 1;
        __syncthreads();
#pragma unroll
        for (int i = 0; i < 4; i++) {
            int r = ar + 16 * i;
            *reinterpret_cast<float4*>(&As[r * 36 + af * 4]) = areg[i];
        }
        CP_WAIT0();
        __syncthreads();
        if (kt < 7) {
            loadB(cur ^ 1, (kt + 1) * 32);
            ldgA((kt + 1) * 32);
        }

#pragma unroll
        for (int kk = 0; kk < 32; kk += 8) {
            uint32_t Ab[2][4], Al[2][4];
#pragma unroll
            for (int mt = 0; mt < 2; mt++) {
                int r  = wm * 32 + mt * 16 + (lane >> 2);
                int cb = kk + (lane & 3);
                float f0 = As[r * 36 + cb];
                float f1 = As[(r + 8) * 36 + cb];
                float f2 = As[r * 36 + cb + 4];
                float f3 = As[(r + 8) * 36 + cb + 4];
                Ab[mt][0] = f2tf(f0); Al[mt][0] = f2tf(f0 - __uint_as_float(Ab[mt][0]));
                Ab[mt][1] = f2tf(f1); Al[mt][1] = f2tf(f1 - __uint_as_float(Ab[mt][1]));
                Ab[mt][2] = f2tf(f2); Al[mt][2] = f2tf(f2 - __uint_as_float(Ab[mt][2]));
                Ab[mt][3] = f2tf(f3); Al[mt][3] = f2tf(f3 - __uint_as_float(Ab[mt][3]));
            }
#pragma unroll
            for (int nt = 0; nt < 8; nt++) {
                int cn = wn * 64 + nt * 8 + (lane >> 2);
                int rk = kk + (lane & 3);
                float g0 = Bs[cur][rk * 132 + cn];
                float g1 = Bs[cur][(rk + 4) * 132 + cn];
                uint32_t Bb0 = f2tf(g0), Bb1 = f2tf(g1);
                uint32_t Bl0 = f2tf(g0 - __uint_as_float(Bb0));
                uint32_t Bl1 = f2tf(g1 - __uint_as_float(Bb1));
#pragma unroll
                for (int mt = 0; mt < 2; mt++) {
                    MMA_TF32(c[mt][nt], Ab[mt][0], Ab[mt][1], Ab[mt][2], Ab[mt][3], Bb0, Bb1);
                    MMA_TF32(c[mt][nt], Ab[mt][0], Ab[mt][1], Ab[mt][2], Ab[mt][3], Bl0, Bl1);
                    MMA_TF32(c[mt][nt], Al[mt][0], Al[mt][1], Al[mt][2], Al[mt][3], Bb0, Bb1);
                }
            }
        }
    }

#pragma unroll
    for (int mt = 0; mt < 2; mt++) {
        int row = m0 + wm * 32 + mt * 16 + (lane >> 2);
        float z0 = g_invZ[row], z1 = g_invZ[row + 8];
#pragma unroll
        for (int nt = 0; nt < 8; nt++) {
            int col = n0 + wn * 64 + nt * 8 + 2 * (lane & 3);
            *reinterpret_cast<float2*>(&Cout[(size_t)row * DIM + col]) =
                make_float2(c[mt][nt][0] * z0, c[mt][nt][1] * z0);
            *reinterpret_cast<float2*>(&Cout[(size_t)(row + 8) * DIM + col]) =
                make_float2(c[mt][nt][2] * z1, c[mt][nt][3] * z1);
        }
    }
}

// ---------------- LAUNCH 3: FUSED scan + attention (unchanged from R16) ----------
__global__ void __launch_bounds__(128) fused_attn_kernel(const float* __restrict__ adj)
{
    __shared__ int pbuf_s[4][32 * LSTRIDE];
    __shared__ int elist_s[4][MAXDEG + 8];

    int w    = threadIdx.x >> 5;
    int lane = threadIdx.x & 31;
    int i    = blockIdx.x * 4 + w;
    int* pbuf  = &pbuf_s[w][lane * LSTRIDE];
    int* elist = elist_s[w];

    float ua[8];
    {
        const float4* up = reinterpret_cast<const float4*>(&g_U[(size_t)i * DIM + lane * 8]);
        *reinterpret_cast<float4*>(ua)     = up[0];
        *reinterpret_cast<float4*>(ua + 4) = up[1];
    }

    const uint4* row = reinterpret_cast<const uint4*>(adj + (size_t)i * N_NODES);
    int cntl = 0;
    for (int s0 = 0; s0 < 64; s0 += 8) {
        uint4 v[8];
#pragma unroll
        for (int k = 0; k < 8; k++)
            v[k] = __ldcs(row + lane + (s0 + k) * 32);
#pragma unroll
        for (int k = 0; k < 8; k += 2) {
            uint4 a = v[k], b = v[k + 1];
            if ((a.x | a.y | a.z | a.w) | (b.x | b.y | b.z | b.w)) {
                int jb = (lane + (s0 + k) * 32) << 2;
                if (a.x) { if (cntl < LSLOT) pbuf[cntl] = jb;     cntl++; }
                if (a.y) { if (cntl < LSLOT) pbuf[cntl] = jb + 1; cntl++; }
                if (a.z) { if (cntl < LSLOT) pbuf[cntl] = jb + 2; cntl++; }
                if (a.w) { if (cntl < LSLOT) pbuf[cntl] = jb + 3; cntl++; }
                int jc = jb + 128;
                if (b.x) { if (cntl < LSLOT) pbuf[cntl] = jc;     cntl++; }
                if (b.y) { if (cntl < LSLOT) pbuf[cntl] = jc + 1; cntl++; }
                if (b.z) { if (cntl < LSLOT) pbuf[cntl] = jc + 2; cntl++; }
                if (b.w) { if (cntl < LSLOT) pbuf[cntl] = jc + 3; cntl++; }
            }
        }
    }
    if (cntl > LSLOT) cntl = LSLOT;

    int off = cntl;
#pragma unroll
    for (int d = 1; d < 32; d <<= 1) {
        int n = __shfl_up_sync(0xffffffffu, off, d);
        if (lane >= d) off += n;
    }
    int total = __shfl_sync(0xffffffffu, off, 31);
    off -= cntl;
    int ecnt = (total < MAXDEG) ? total : MAXDEG;

    for (int k = 0; k < cntl; k++) {
        int p = off + k;
        if (p < MAXDEG) elist[p] = pbuf[k];
    }
    __syncwarp();

    int padded = (ecnt + 7) & ~7;
    if (ecnt + lane < padded) elist[ecnt + lane] = N_NODES;
    __syncwarp();

    float acc[8];
#pragma unroll
    for (int k = 0; k < 8; k++) acc[k] = 0.f;
    float z = 0.f;

    for (int e = 0; e < padded; e += 8) {
        uint4 r[8];
#pragma unroll
        for (int q = 0; q < 8; q++) {
            int j = elist[e + q];
            r[q] = *reinterpret_cast<const uint4*>(&g_Hh[(size_t)j * DIM + lane * 8]);
        }

#pragma unroll
        for (int g = 0; g < 2; g++) {
            float e0[8], e1[8], e2[8], e3[8];
            cvt8(e0, r[4 * g + 0]);
            cvt8(e1, r[4 * g + 1]);
            cvt8(e2, r[4 * g + 2]);
            cvt8(e3, r[4 * g + 3]);

            float p0 = 0.f, p1 = 0.f, p2 = 0.f, p3 = 0.f;
#pragma unroll
            for (int k = 0; k < 8; k++) {
                p0 += ua[k] * e0[k];
                p1 += ua[k] * e1[k];
                p2 += ua[k] * e2[k];
                p3 += ua[k] * e3[k];
            }

            float a0 = p0 + __shfl_xor_sync(0xffffffffu, p0, 16);
            float a1 = p1 + __shfl_xor_sync(0xffffffffu, p1, 16);
            float a2 = p2 + __shfl_xor_sync(0xffffffffu, p2, 16);
            float a3 = p3 + __shfl_xor_sync(0xffffffffu, p3, 16);
            bool hi16 = (lane & 16) != 0;
            float b = hi16 ? a1 : a0;
            float c = hi16 ? a3 : a2;
            b += __shfl_xor_sync(0xffffffffu, b, 8);
            c += __shfl_xor_sync(0xffffffffu, c, 8);
            float d = (lane & 8) ? c : b;
            d += __shfl_xor_sync(0xffffffffu, d, 4);
            d += __shfl_xor_sync(0xffffffffu, d, 2);
            d += __shfl_xor_sync(0xffffffffu, d, 1);

            float wv = __expf(d * 0.0625f) - 1.0f;
            float w0 = __shfl_sync(0xffffffffu, wv, 0);
            float w1 = __shfl_sync(0xffffffffu, wv, 16);
            float w2 = __shfl_sync(0xffffffffu, wv, 8);
            float w3 = __shfl_sync(0xffffffffu, wv, 24);
            z += (w0 + w1) + (w2 + w3);

#pragma unroll
            for (int k = 0; k < 8; k++)
                acc[k] += w0 * e0[k] + w1 * e1[k] + w2 * e2[k] + w3 * e3[k];
        }
    }

    const float4* hs = reinterpret_cast<const float4*>(&g_Hsum[lane * 8]);
    float4 h0 = hs[0], h1 = hs[1];
    float4 y0 = make_float4(h0.x + acc[0], h0.y + acc[1], h0.z + acc[2], h0.w + acc[3]);
    float4 y1 = make_float4(h1.x + acc[4], h1.y + acc[5], h1.z + acc[6], h1.w + acc[7]);
    float4* yp = reinterpret_cast<float4*>(&g_Y[(size_t)i * DIM + lane * 8]);
    yp[0] = y0;
    yp[1] = y1;

    if (lane == 0) g_invZ[i] = 1.0f / ((float)N_NODES + z);
}

// ---------------- launch ---------------------------------------------------------
extern "C" void kernel_launch(void* const* d_in, const int* in_sizes, int n_in,
                              void* d_out, int out_size)
{
    const float* adj = (const float*)d_in[0];
    const float* h   = (const float*)d_in[1];
    const float* Wq  = (const float*)d_in[2];
    const float* Wk  = (const float*)d_in[3];
    const float* Wv  = (const float*)d_in[4];
    float* out = (float*)d_out;

    setup_kernel<<<2561, 256>>>(h, Wq, Wk, Wv);   // prep | conv | hsum_part | pad
    gemm0_kernel<<<257, 128>>>(h);                // U = Hh @ Mht^T (fp16) | hsum_final
    fused_attn_kernel<<<2048, 128>>>(adj);
    gemm1_kernel<<<256, 128>>>(out);              // 4th launch -> ncu slot
}